// round 2
// baseline (speedup 1.0000x reference)
#include <cuda_runtime.h>
#include <math.h>

#define NN 50000
#define NE 1600000
#define PAD 129

#define A_SZ (144 * PAD)
#define B_SZ (128 * PAD)
#define W_SZ 9216
#define SM_FLOATS (A_SZ + B_SZ + W_SZ + 256)
#define SM_BYTES (SM_FLOATS * 4)

__device__ float g_nf1[NN * 32];
__device__ float g_nf2[NN * 32];

__device__ __forceinline__ void atomicMaxF(float* a, float v) {
    if (v >= 0.f) atomicMax((int*)a, __float_as_int(v));
    else          atomicMin((unsigned int*)a, (unsigned int)__float_as_int(v));
}

__device__ __forceinline__ void stageW(float* Ws, const float* __restrict__ Wg, int n, int t) {
    const float4* s = (const float4*)Wg;
    float4* d = (float4*)Ws;
    for (int i = t; i < n / 4; i += 256) d[i] = s[i];
}

// C[m][n] = sum_k A[k][m] * W[k][n] + bias[n], A/C feature-major with stride PAD.
// 256 threads: tm = t&31 covers m in {tm, tm+32, tm+64, tm+96}; tn = t>>5 covers
// n in [tn*NT, tn*NT+NT).  W in smem row-major [K][N] (broadcast across warp).
template<int K, int N, int NT, bool RELU>
__device__ __forceinline__ void gemm(const float* A, const float* Ws,
                                     const float* __restrict__ bias, float* C, int t) {
    const int tm = t & 31;
    const int n0 = (t >> 5) * NT;
    float acc[4][NT];
#pragma unroll
    for (int j = 0; j < NT; j++) {
        float b = (N % NT == 0 || n0 + j < N) ? bias[n0 + j] : 0.f;
#pragma unroll
        for (int p = 0; p < 4; p++) acc[p][j] = b;
    }
#pragma unroll 4
    for (int k = 0; k < K; k++) {
        float a0 = A[k * PAD + tm];
        float a1 = A[k * PAD + tm + 32];
        float a2 = A[k * PAD + tm + 64];
        float a3 = A[k * PAD + tm + 96];
        const float* wr = Ws + k * N + n0;
#pragma unroll
        for (int j = 0; j < NT; j++) {
            float w = (N % NT == 0 || n0 + j < N) ? wr[j] : 0.f;
            acc[0][j] = fmaf(a0, w, acc[0][j]);
            acc[1][j] = fmaf(a1, w, acc[1][j]);
            acc[2][j] = fmaf(a2, w, acc[2][j]);
            acc[3][j] = fmaf(a3, w, acc[3][j]);
        }
    }
#pragma unroll
    for (int j = 0; j < NT; j++) {
        if (N % NT == 0 || n0 + j < N) {
            float* cr = C + (n0 + j) * PAD + tm;
#pragma unroll
            for (int p = 0; p < 4; p++) {
                float v = acc[p][j];
                if (RELU) v = fmaxf(v, 0.2f * v);
                cr[p * 32] = v;
            }
        }
    }
}

extern "C" __global__ void __launch_bounds__(256)
edge_kernel(const float* __restrict__ nf, const float* __restrict__ ef,
            const int* __restrict__ src, const int* __restrict__ dst,
            const float* __restrict__ Wm1, const float* __restrict__ bm1,
            const float* __restrict__ Wm2, const float* __restrict__ bm2,
            const float* __restrict__ Wm3, const float* __restrict__ bm3,
            const float* __restrict__ Wm4, const float* __restrict__ bm4) {
    extern __shared__ float sm[];
    float* A  = sm;
    float* B  = sm + A_SZ;
    float* Ws = sm + A_SZ + B_SZ;
    int*  sidx = (int*)(sm + A_SZ + B_SZ + W_SZ);

    const int t = threadIdx.x;
    const int wid = t >> 5, lane = t & 31;
    const int e0 = blockIdx.x * 128;

    if (t < 128) sidx[t] = src[e0 + t];
    else         sidx[t] = dst[e0 + t - 128];
    __syncthreads();

    // gather: X = [nf[src] | nf[dst] | ef] -> A feature-major [144][PAD]
    for (int m = wid; m < 128; m += 8) {
        int s = sidx[m];
        A[lane * PAD + m]        = nf[s * 64 + lane];
        A[(lane + 32) * PAD + m] = nf[s * 64 + 32 + lane];
        int d = sidx[128 + m];
        A[(64 + lane) * PAD + m] = nf[d * 64 + lane];
        A[(96 + lane) * PAD + m] = nf[d * 64 + 32 + lane];
        if (lane < 16) A[(128 + lane) * PAD + m] = ef[(e0 + m) * 16 + lane];
    }
    __syncthreads();

    stageW(Ws, Wm1, 144 * 64, t);  __syncthreads();
    gemm<144, 64, 8, true>(A, Ws, bm1, B, t);  __syncthreads();
    stageW(Ws, Wm2, 64 * 128, t);  __syncthreads();
    gemm<64, 128, 16, true>(B, Ws, bm2, A, t); __syncthreads();
    stageW(Ws, Wm3, 128 * 64, t);  __syncthreads();
    gemm<128, 64, 8, true>(A, Ws, bm3, B, t);  __syncthreads();
    stageW(Ws, Wm4, 64 * 65, t);   __syncthreads();
    gemm<64, 65, 9, false>(B, Ws, bm4, A, t);  __syncthreads();

    // gate + scatter: k = sigmoid(row 0); rows 1..32 -> sum, rows 33..64 -> max
    for (int idx = t; idx < 128 * 32; idx += 256) {
        int m = idx >> 5, h = idx & 31;
        float g = 1.f / (1.f + expf(-A[m]));
        int d = sidx[128 + m];
        atomicAdd(&g_nf1[d * 32 + h], A[(1 + h) * PAD + m] * g);
        atomicMaxF(&g_nf2[d * 32 + h], A[(33 + h) * PAD + m] * g);
    }
}

extern "C" __global__ void __launch_bounds__(256)
node_kernel(const float* __restrict__ nf,
            const float* __restrict__ Wr1, const float* __restrict__ br1,
            const float* __restrict__ Wr2, const float* __restrict__ br2,
            const float* __restrict__ Wr3, const float* __restrict__ br3,
            const float* __restrict__ Wr4, const float* __restrict__ br4,
            float* __restrict__ out) {
    extern __shared__ float sm[];
    float* A  = sm;
    float* B  = sm + A_SZ;
    float* Ws = sm + A_SZ + B_SZ;

    const int t = threadIdx.x;
    const int wid = t >> 5, lane = t & 31;
    const int n0 = blockIdx.x * 128;
    const int cnt = min(128, NN - n0);

    // gather: Y = [nf | nf1 | nf2(fixed)] -> A feature-major [128][PAD]
    for (int m = wid; m < cnt; m += 8) {
        int nd = n0 + m;
        A[lane * PAD + m]        = nf[nd * 64 + lane];
        A[(lane + 32) * PAD + m] = nf[nd * 64 + 32 + lane];
        A[(64 + lane) * PAD + m] = g_nf1[nd * 32 + lane];
        float v = g_nf2[nd * 32 + lane];
        A[(96 + lane) * PAD + m] = isfinite(v) ? v : 0.f;
    }
    __syncthreads();

    stageW(Ws, Wr1, 128 * 64, t);  __syncthreads();
    gemm<128, 64, 8, true>(A, Ws, br1, B, t);  __syncthreads();
    stageW(Ws, Wr2, 64 * 128, t);  __syncthreads();
    gemm<64, 128, 16, true>(B, Ws, br2, A, t); __syncthreads();
    stageW(Ws, Wr3, 128 * 64, t);  __syncthreads();
    gemm<128, 64, 8, true>(A, Ws, br3, B, t);  __syncthreads();
    stageW(Ws, Wr4, 64 * 64, t);   __syncthreads();
    gemm<64, 64, 8, false>(B, Ws, br4, A, t);  __syncthreads();

    for (int idx = t; idx < 128 * 64; idx += 256) {
        int m = idx >> 6, n = idx & 63;
        if (m < cnt) out[(n0 + m) * 64 + n] = A[n * PAD + m];
    }
}

extern "C" __global__ void init_kernel() {
    int i = blockIdx.x * blockDim.x + threadIdx.x;
    if (i < NN * 32) {
        g_nf1[i] = 0.f;
        g_nf2[i] = -INFINITY;
    }
}

extern "C" void kernel_launch(void* const* d_in, const int* in_sizes, int n_in,
                              void* d_out, int out_size) {
    (void)in_sizes; (void)n_in; (void)out_size;
    const float* nf = (const float*)d_in[0];
    const float* ef = (const float*)d_in[1];
    const int* src  = (const int*)d_in[2];
    const int* dst  = (const int*)d_in[3];

    cudaFuncSetAttribute(edge_kernel, cudaFuncAttributeMaxDynamicSharedMemorySize, SM_BYTES);
    cudaFuncSetAttribute(node_kernel, cudaFuncAttributeMaxDynamicSharedMemorySize, SM_BYTES);

    init_kernel<<<(NN * 32 + 255) / 256, 256>>>();

    edge_kernel<<<NE / 128, 256, SM_BYTES>>>(
        nf, ef, src, dst,
        (const float*)d_in[4], (const float*)d_in[5],
        (const float*)d_in[6], (const float*)d_in[7],
        (const float*)d_in[8], (const float*)d_in[9],
        (const float*)d_in[10], (const float*)d_in[11]);

    node_kernel<<<(NN + 127) / 128, 256, SM_BYTES>>>(
        nf,
        (const float*)d_in[12], (const float*)d_in[13],
        (const float*)d_in[14], (const float*)d_in[15],
        (const float*)d_in[16], (const float*)d_in[17],
        (const float*)d_in[18], (const float*)d_in[19],
        (float*)d_out);
}